// round 2
// baseline (speedup 1.0000x reference)
#include <cuda_runtime.h>
#include <math.h>

// Problem constants
#define NSAMP 4096
#define LATD  64
#define GD    2016
#define LDF   65   // padded leading dim for 64x64 smem matrices

// Output layout: recons [4096,64], pred [4096,2], latent [4096,64], concatenated
#define REC_OFF  0
#define PRED_OFF (NSAMP * 64)            // 262144
#define LAT_OFF  (NSAMP * 64 + NSAMP*2)  // 270336

// Scratch: per-sample skew matrix A (diagonal entries never written; masked on read)
__device__ float g_A[(size_t)NSAMP * LATD * LATD];

// ---------------------------------------------------------------------------
// Kernel 1: A[n][r][c] = -(gi_latent[n] . W_up[p] + b_up[p]),  A[n][c][r] = +val
// for p = tril pair index (r>c).  GEMM: [4096,64] x [64,2016]^T, 64x64 tiles.
// ---------------------------------------------------------------------------
__global__ __launch_bounds__(256) void k_buildA(
    const float* __restrict__ gi,
    const float* __restrict__ Wup,
    const float* __restrict__ bup)
{
    __shared__ float sG[64 * LDF];  // gi tile, row-major [s][k], lda 65
    __shared__ float sW[64 * LDF];  // W_up tile, row-major [p][k], lda 65

    const int tid  = threadIdx.x;
    const int pIdx = blockIdx.x * 64;   // pair tile base
    const int sIdx = blockIdx.y * 64;   // sample tile base

    // Cooperative tile load (coalesced global, conflict-free STS: stride-65 rows)
    for (int lin = tid; lin < 4096; lin += 256) {
        int row = lin >> 6, k = lin & 63;
        sG[row * LDF + k] = gi[(sIdx + row) * 64 + k];
        int p = pIdx + row;
        sW[row * LDF + k] = (p < GD) ? Wup[p * 64 + k] : 0.0f;
    }
    __syncthreads();

    // 4x4 register tile per thread; items interleaved by 16 so that per
    // instruction the 16 lane-distinct smem addresses hit distinct banks.
    const int cg = tid & 15;   // pair lane
    const int rg = tid >> 4;   // sample lane

    float acc[4][4];
#pragma unroll
    for (int a = 0; a < 4; ++a)
#pragma unroll
        for (int b = 0; b < 4; ++b) acc[a][b] = 0.0f;

#pragma unroll 8
    for (int k = 0; k < 64; ++k) {
        float Ar[4], Br[4];
#pragma unroll
        for (int a = 0; a < 4; ++a) Ar[a] = sG[(rg + 16 * a) * LDF + k];
#pragma unroll
        for (int b = 0; b < 4; ++b) Br[b] = sW[(cg + 16 * b) * LDF + k];
#pragma unroll
        for (int a = 0; a < 4; ++a)
#pragma unroll
            for (int b = 0; b < 4; ++b)
                acc[a][b] = fmaf(Ar[a], Br[b], acc[a][b]);
    }

    // Epilogue: add bias, map pair p -> (r,c), scatter +/- into g_A
#pragma unroll
    for (int b = 0; b < 4; ++b) {
        int p = pIdx + cg + 16 * b;
        if (p >= GD) continue;
        float bb = bup[p];
        // r = max r with r(r-1)/2 <= p
        float t = sqrtf(8.0f * (float)p + 1.0f);
        int r = (int)((1.0f + t) * 0.5f);
        while (r * (r - 1) / 2 > p) --r;
        while ((r + 1) * r / 2 <= p) ++r;
        int c = p - r * (r - 1) / 2;
#pragma unroll
        for (int a = 0; a < 4; ++a) {
            int s = sIdx + rg + 16 * a;
            float v = acc[a][b] + bb;
            float* An = g_A + (size_t)s * 4096;
            An[r * 64 + c] = -v;   // A[r][c] = -vec (r>c)
            An[c * 64 + r] =  v;   // A[c][r] = +vec
        }
    }
}

// ---------------------------------------------------------------------------
// Kernel 2: per sample (64 threads):
//   B = I - A (smem, column-major lda 65) -> in-place LU (no pivoting; pivots>=1
//   since sym(B)=I and Schur complements preserve sym>=I)
//   y    = B^-T li          (U^T forward, L^T backward)
//   mis  = Q^T y = y + A^T y
//   h    = relu(W1 mis + b1);  fc2 = W2 h + b2
//   w    = Q fc2 = fc2 + A fc2
//   latent = B^-1 w         (L forward, U backward)
//   recons = W4 relu(W3 latent + b3) + b4
//   pred   = W6 relu(W5 latent + b5) + b6
// ---------------------------------------------------------------------------
__global__ __launch_bounds__(64) void k_solve(
    const float* __restrict__ li,
    const float* __restrict__ W1, const float* __restrict__ b1,
    const float* __restrict__ W2, const float* __restrict__ b2,
    const float* __restrict__ W3, const float* __restrict__ b3,
    const float* __restrict__ W4, const float* __restrict__ b4,
    const float* __restrict__ W5, const float* __restrict__ b5,
    const float* __restrict__ W6, const float* __restrict__ b6,
    float* __restrict__ out)
{
    __shared__ float Fs[64 * LDF];  // F(i,j) at Fs[j*LDF + i]  (column-major)
    __shared__ float xv[64];
    __shared__ float yv[64];
    __shared__ float v1[64];
    __shared__ float v2[64];

    const int n   = blockIdx.x;
    const int tid = threadIdx.x;
    const float* __restrict__ An = g_A + (size_t)n * 4096;

    // Build B = I - A (diagonal of g_A is stale -> masked)
    for (int i = 0; i < 64; ++i) {
        float a = An[i * 64 + tid];            // coalesced
        float b = (i == tid) ? 1.0f : -a;
        Fs[tid * LDF + i] = b;                 // F(i, tid); stride-65 STS, no conflicts
    }
    __syncthreads();

    // In-place LU (right-looking). Thread tid handles column entry / row updates
    // of column index tid.
    for (int k = 0; k < 63; ++k) {
        float linv = 1.0f / Fs[k * LDF + k];
        if (tid > k) {
            float l = Fs[k * LDF + tid] * linv;
            Fs[k * LDF + tid] = l;
#pragma unroll 4
            for (int j = k + 1; j < 64; ++j)
                Fs[j * LDF + tid] = fmaf(-l, Fs[j * LDF + k], Fs[j * LDF + tid]);
        }
        __syncthreads();
    }

    // ---- Solve B^T y = li  (B^T = U^T L^T) ----
    float acc = li[n * 64 + tid];
    // forward with U^T (lower, diag = U(k,k)); U(k,i) at Fs[i*LDF+k]
    for (int k = 0; k < 64; ++k) {
        if (tid == k) xv[k] = acc / Fs[k * LDF + k];
        __syncthreads();
        if (tid > k) acc = fmaf(-Fs[tid * LDF + k], xv[k], acc);
    }
    acc = xv[tid];  // own write, visible to self
    // backward with L^T (upper, unit diag); L(k,i) at Fs[i*LDF+k]
    for (int k = 63; k >= 0; --k) {
        if (tid == k) yv[k] = acc;
        __syncthreads();
        if (tid < k) acc = fmaf(-Fs[tid * LDF + k], yv[k], acc);
    }
    __syncthreads();

    // ---- mis = Q^T y = y + A^T y  (skip stale diagonal) ----
    float mval = yv[tid];
#pragma unroll 8
    for (int i = 0; i < 64; ++i) {
        float a = An[i * 64 + tid];            // L1-resident after build pass
        if (i != tid) mval = fmaf(a, yv[i], mval);
    }
    v1[tid] = mval;
    __syncthreads();

    // ---- h = relu(W1 mis + b1) ----
    float h = b1[tid];
    {
        const float* w = W1 + tid * 64;
#pragma unroll 8
        for (int k = 0; k < 64; ++k) h = fmaf(w[k], v1[k], h);
    }
    h = fmaxf(h, 0.0f);
    v2[tid] = h;
    __syncthreads();

    // ---- fc2 = W2 h + b2 ----
    float f2 = b2[tid];
    {
        const float* w = W2 + tid * 64;
#pragma unroll 8
        for (int k = 0; k < 64; ++k) f2 = fmaf(w[k], v2[k], f2);
    }
    v1[tid] = f2;
    __syncthreads();

    // ---- w = Q fc2 = fc2 + A fc2 ----
    float wv = v1[tid];
#pragma unroll 8
    for (int j = 0; j < 64; ++j) {
        float a = An[tid * 64 + j];            // per-thread row stream, L1 hits
        if (j != tid) wv = fmaf(a, v1[j], wv);
    }
    acc = wv;

    // ---- Solve B z = w  (L forward unit, U backward) ----
    for (int k = 0; k < 64; ++k) {
        if (tid == k) xv[k] = acc;
        __syncthreads();
        if (tid > k) acc = fmaf(-Fs[k * LDF + tid], xv[k], acc);
    }
    for (int k = 63; k >= 0; --k) {
        if (tid == k) xv[k] = acc / Fs[k * LDF + k];
        __syncthreads();
        if (tid < k) acc = fmaf(-Fs[k * LDF + tid], xv[k], acc);
    }
    __syncthreads();  // all xv (= latent) visible

    float lat = xv[tid];
    out[LAT_OFF + n * 64 + tid] = lat;

    // ---- recons = W4 relu(W3 latent + b3) + b4 ----
    float t3 = b3[tid];
    {
        const float* w = W3 + tid * 64;
#pragma unroll 8
        for (int k = 0; k < 64; ++k) t3 = fmaf(w[k], xv[k], t3);
    }
    t3 = fmaxf(t3, 0.0f);
    v1[tid] = t3;
    // ---- pred path stage 1: relu(W5 latent + b5) ----
    float t5 = b5[tid];
    {
        const float* w = W5 + tid * 64;
#pragma unroll 8
        for (int k = 0; k < 64; ++k) t5 = fmaf(w[k], xv[k], t5);
    }
    t5 = fmaxf(t5, 0.0f);
    v2[tid] = t5;
    __syncthreads();

    float rec = b4[tid];
    {
        const float* w = W4 + tid * 64;
#pragma unroll 8
        for (int k = 0; k < 64; ++k) rec = fmaf(w[k], v1[k], rec);
    }
    out[REC_OFF + n * 64 + tid] = rec;

    if (tid < 2) {
        float pr = b6[tid];
        const float* w = W6 + tid * 64;
#pragma unroll 8
        for (int k = 0; k < 64; ++k) pr = fmaf(w[k], v2[k], pr);
        out[PRED_OFF + n * 2 + tid] = pr;
    }
}

// ---------------------------------------------------------------------------
extern "C" void kernel_launch(void* const* d_in, const int* in_sizes, int n_in,
                              void* d_out, int out_size)
{
    const float* li  = (const float*)d_in[0];
    const float* gi  = (const float*)d_in[1];
    const float* Wup = (const float*)d_in[2];
    const float* bup = (const float*)d_in[3];
    const float* W1  = (const float*)d_in[4];
    const float* b1  = (const float*)d_in[5];
    const float* W2  = (const float*)d_in[6];
    const float* b2  = (const float*)d_in[7];
    const float* W3  = (const float*)d_in[8];
    const float* b3  = (const float*)d_in[9];
    const float* W4  = (const float*)d_in[10];
    const float* b4  = (const float*)d_in[11];
    const float* W5  = (const float*)d_in[12];
    const float* b5  = (const float*)d_in[13];
    const float* W6  = (const float*)d_in[14];
    const float* b6  = (const float*)d_in[15];
    float* out = (float*)d_out;

    dim3 g1(32, 64);   // 32 pair tiles (2016 -> 32*64 w/ guard) x 64 sample tiles
    k_buildA<<<g1, 256>>>(gi, Wup, bup);

    k_solve<<<NSAMP, 64>>>(li, W1, b1, W2, b2, W3, b3, W4, b4, W5, b5, W6, b6, out);
}

// round 4
// speedup vs baseline: 2.2808x; 2.2808x over previous
#include <cuda_runtime.h>
#include <math.h>

// Problem constants
#define NSAMP 4096
#define GD    2016
#define LDF   65

// Output layout: recons [4096,64], pred [4096,2], latent [4096,64]
#define REC_OFF  0
#define PRED_OFF (NSAMP * 64)
#define LAT_OFF  (NSAMP * 64 + NSAMP * 2)

// Scratch: per-sample skew matrix A (diagonal stale; masked on read)
__device__ float g_A[(size_t)NSAMP * 4096];
// Transposed MLP weights: W1,W2,W3,W4,W5 (each 64x64, stored [j][i])
__device__ float g_Wt[5 * 4096];

// ---------------------------------------------------------------------------
// Kernel 1 (proven in R2): A scatter from GEMM gi @ W_up^T + b_up
// ---------------------------------------------------------------------------
__global__ __launch_bounds__(256) void k_buildA(
    const float* __restrict__ gi,
    const float* __restrict__ Wup,
    const float* __restrict__ bup)
{
    __shared__ float sG[64 * LDF];
    __shared__ float sW[64 * LDF];

    const int tid  = threadIdx.x;
    const int pIdx = blockIdx.x * 64;
    const int sIdx = blockIdx.y * 64;

    for (int lin = tid; lin < 4096; lin += 256) {
        int row = lin >> 6, k = lin & 63;
        sG[row * LDF + k] = gi[(sIdx + row) * 64 + k];
        int p = pIdx + row;
        sW[row * LDF + k] = (p < GD) ? Wup[p * 64 + k] : 0.0f;
    }
    __syncthreads();

    const int cg = tid & 15;
    const int rg = tid >> 4;

    float acc[4][4];
#pragma unroll
    for (int a = 0; a < 4; ++a)
#pragma unroll
        for (int b = 0; b < 4; ++b) acc[a][b] = 0.0f;

#pragma unroll 8
    for (int k = 0; k < 64; ++k) {
        float Ar[4], Br[4];
#pragma unroll
        for (int a = 0; a < 4; ++a) Ar[a] = sG[(rg + 16 * a) * LDF + k];
#pragma unroll
        for (int b = 0; b < 4; ++b) Br[b] = sW[(cg + 16 * b) * LDF + k];
#pragma unroll
        for (int a = 0; a < 4; ++a)
#pragma unroll
            for (int b = 0; b < 4; ++b)
                acc[a][b] = fmaf(Ar[a], Br[b], acc[a][b]);
    }

#pragma unroll
    for (int b = 0; b < 4; ++b) {
        int p = pIdx + cg + 16 * b;
        if (p >= GD) continue;
        float bb = bup[p];
        float t = sqrtf(8.0f * (float)p + 1.0f);
        int r = (int)((1.0f + t) * 0.5f);
        while (r * (r - 1) / 2 > p) --r;
        while ((r + 1) * r / 2 <= p) ++r;
        int c = p - r * (r - 1) / 2;
#pragma unroll
        for (int a = 0; a < 4; ++a) {
            int s = sIdx + rg + 16 * a;
            float v = acc[a][b] + bb;
            float* An = g_A + (size_t)s * 4096;
            An[r * 64 + c] = -v;
            An[c * 64 + r] =  v;
        }
    }
}

// ---------------------------------------------------------------------------
// Prep: transpose the 5 small MLP weight matrices into g_Wt [j][i]
// ---------------------------------------------------------------------------
__global__ __launch_bounds__(256) void k_prep(
    const float* __restrict__ W1, const float* __restrict__ W2,
    const float* __restrict__ W3, const float* __restrict__ W4,
    const float* __restrict__ W5)
{
    int idx = blockIdx.x * 256 + threadIdx.x;   // 0..20479
    if (idx >= 5 * 4096) return;
    int m = idx >> 12;
    int r = idx & 4095;
    int i = r >> 6, j = r & 63;
    const float* W = (m == 0) ? W1 : (m == 1) ? W2 : (m == 2) ? W3 : (m == 3) ? W4 : W5;
    g_Wt[m * 4096 + j * 64 + i] = W[i * 64 + j];
}

// ---------------------------------------------------------------------------
// Register-resident warp LU / solve / matvec primitives
// Lane owns rows (lane) -> r0[], (lane+32) -> r1[]. All indices static.
// ---------------------------------------------------------------------------
#define FULLM 0xffffffffu

__device__ __forceinline__ void lu64(float (&r0)[64], float (&r1)[64],
                                     float& dinv0, float& dinv1, int lane)
{
#pragma unroll
    for (int k = 0; k < 63; ++k) {
        if (k < 32) {
            float piv  = __shfl_sync(FULLM, r0[k], k);
            float pinv = 1.0f / piv;
            dinv0 = (lane == k) ? pinv : dinv0;
            float l0 = (lane > k) ? r0[k] * pinv : 0.0f;  // 0 => update is no-op
            r0[k] = (lane > k) ? l0 : r0[k];
            float l1 = r1[k] * pinv;                      // rows 32.. always below pivot
            r1[k] = l1;
#pragma unroll
            for (int j = k + 1; j < 64; ++j) {
                float bj = __shfl_sync(FULLM, r0[j], k);
                r0[j] = fmaf(-l0, bj, r0[j]);
                r1[j] = fmaf(-l1, bj, r1[j]);
            }
        } else {
            float piv  = __shfl_sync(FULLM, r1[k], k - 32);
            float pinv = 1.0f / piv;
            dinv1 = (lane == k - 32) ? pinv : dinv1;
            float l1 = (lane > k - 32) ? r1[k] * pinv : 0.0f;
            r1[k] = (lane > k - 32) ? l1 : r1[k];
#pragma unroll
            for (int j = k + 1; j < 64; ++j) {
                float bj = __shfl_sync(FULLM, r1[j], k - 32);
                r1[j] = fmaf(-l1, bj, r1[j]);
            }
        }
    }
    {   // last pivot (row 63)
        float piv  = __shfl_sync(FULLM, r1[63], 31);
        float pinv = 1.0f / piv;
        dinv1 = (lane == 31) ? pinv : dinv1;
    }
}

// Solve (LU) x = b.  b/x distributed: lane holds indices lane and lane+32.
__device__ __forceinline__ void solve64(const float (&r0)[64], const float (&r1)[64],
                                        float dinv0, float dinv1, int lane,
                                        float b0, float b1, float& x0, float& x1)
{
    float a0 = b0, a1 = b1;
    // forward: L z = b (unit lower)
#pragma unroll
    for (int k = 0; k < 64; ++k) {
        if (k < 32) {
            float zk = __shfl_sync(FULLM, a0, k);
            a0 = (lane > k) ? fmaf(-r0[k], zk, a0) : a0;
            a1 = fmaf(-r1[k], zk, a1);
        } else {
            float zk = __shfl_sync(FULLM, a1, k - 32);
            a1 = (lane > k - 32) ? fmaf(-r1[k], zk, a1) : a1;
        }
    }
    // backward: U x = z
#pragma unroll
    for (int k = 63; k >= 0; --k) {
        if (k >= 32) {
            float xk = __shfl_sync(FULLM, a1 * dinv1, k - 32);
            x1 = (lane == k - 32) ? xk : x1;
            a1 = (lane < k - 32) ? fmaf(-r1[k], xk, a1) : a1;
            a0 = fmaf(-r0[k], xk, a0);     // all rows t<32 < k
        } else {
            float xk = __shfl_sync(FULLM, a0 * dinv0, k);
            x0 = (lane == k) ? xk : x0;
            a0 = (lane < k) ? fmaf(-r0[k], xk, a0) : a0;
        }
    }
}

// y = W x with Wt pre-transposed: y_i = sum_j Wt[j*64+i] * x_j
__device__ __forceinline__ void matvec64(const float* __restrict__ Wt, int lane,
                                         float x0, float x1, float& y0, float& y1)
{
    float a0 = 0.0f, a1 = 0.0f;
#pragma unroll
    for (int j = 0; j < 64; ++j) {
        float xj = (j < 32) ? __shfl_sync(FULLM, x0, j)
                            : __shfl_sync(FULLM, x1, j - 32);
        a0 = fmaf(Wt[j * 64 + lane],      xj, a0);
        a1 = fmaf(Wt[j * 64 + lane + 32], xj, a1);
    }
    y0 = a0; y1 = a1;
}

// ---------------------------------------------------------------------------
// Kernel 2: warp-per-sample, register LU, no smem, no block barriers.
//   u = Q^{-1} li,  mis = 2u - li           (Q = I + A = B^T)
//   h = relu(W1 mis + b1); fc2 = W2 h + b2
//   v = B^{-1} fc2, latent = 2v - fc2       (B = I - A)
//   recons = W4 relu(W3 latent + b3) + b4
//   pred   = W6 relu(W5 latent + b5) + b6
// ---------------------------------------------------------------------------
__global__ __launch_bounds__(128) void k_warp(
    const float* __restrict__ li,
    const float* __restrict__ b1v, const float* __restrict__ b2v,
    const float* __restrict__ b3v, const float* __restrict__ b4v,
    const float* __restrict__ b5v,
    const float* __restrict__ W6,  const float* __restrict__ b6v,
    float* __restrict__ out)
{
    const int lane = threadIdx.x & 31;
    const int n    = blockIdx.x * 4 + (threadIdx.x >> 5);
    const float* __restrict__ An = g_A + (size_t)n * 4096;

    float r0[64], r1[64];
    float dinv0 = 1.0f, dinv1 = 1.0f;

    // ---- Build Q = I + A.  A(t,j) = -A(j,t) = -An[j*64+t]  (coalesced reads)
#pragma unroll
    for (int j = 0; j < 64; ++j) {
        float a0 = An[j * 64 + lane];
        float a1 = An[j * 64 + lane + 32];
        r0[j] = (j == lane)      ? 1.0f : -a0;
        r1[j] = (j == lane + 32) ? 1.0f : -a1;
    }
    lu64(r0, r1, dinv0, dinv1, lane);

    float li0 = li[n * 64 + lane];
    float li1 = li[n * 64 + lane + 32];
    float u0 = 0.0f, u1 = 0.0f;
    solve64(r0, r1, dinv0, dinv1, lane, li0, li1, u0, u1);
    float m0 = 2.0f * u0 - li0;
    float m1 = 2.0f * u1 - li1;

    // ---- MLP core
    float h0, h1;
    matvec64(g_Wt + 0 * 4096, lane, m0, m1, h0, h1);
    h0 = fmaxf(h0 + b1v[lane], 0.0f);
    h1 = fmaxf(h1 + b1v[lane + 32], 0.0f);
    float f0, f1;
    matvec64(g_Wt + 1 * 4096, lane, h0, h1, f0, f1);
    f0 += b2v[lane];
    f1 += b2v[lane + 32];

    // ---- Build B = I - A.  B(t,j) = +An[j*64+t] off-diagonal
#pragma unroll
    for (int j = 0; j < 64; ++j) {
        float a0 = An[j * 64 + lane];
        float a1 = An[j * 64 + lane + 32];
        r0[j] = (j == lane)      ? 1.0f : a0;
        r1[j] = (j == lane + 32) ? 1.0f : a1;
    }
    dinv0 = 1.0f; dinv1 = 1.0f;
    lu64(r0, r1, dinv0, dinv1, lane);

    float v0 = 0.0f, v1 = 0.0f;
    solve64(r0, r1, dinv0, dinv1, lane, f0, f1, v0, v1);
    float L0 = 2.0f * v0 - f0;
    float L1 = 2.0f * v1 - f1;
    out[LAT_OFF + n * 64 + lane]      = L0;
    out[LAT_OFF + n * 64 + lane + 32] = L1;

    // ---- recons
    float t30, t31;
    matvec64(g_Wt + 2 * 4096, lane, L0, L1, t30, t31);
    t30 = fmaxf(t30 + b3v[lane], 0.0f);
    t31 = fmaxf(t31 + b3v[lane + 32], 0.0f);
    float rc0, rc1;
    matvec64(g_Wt + 3 * 4096, lane, t30, t31, rc0, rc1);
    out[REC_OFF + n * 64 + lane]      = rc0 + b4v[lane];
    out[REC_OFF + n * 64 + lane + 32] = rc1 + b4v[lane + 32];

    // ---- pred
    float t50, t51;
    matvec64(g_Wt + 4 * 4096, lane, L0, L1, t50, t51);
    t50 = fmaxf(t50 + b5v[lane], 0.0f);
    t51 = fmaxf(t51 + b5v[lane + 32], 0.0f);
    float p0 = W6[lane] * t50      + W6[32 + lane] * t51;
    float p1 = W6[64 + lane] * t50 + W6[96 + lane] * t51;
#pragma unroll
    for (int off = 16; off; off >>= 1) {
        p0 += __shfl_xor_sync(FULLM, p0, off);
        p1 += __shfl_xor_sync(FULLM, p1, off);
    }
    if (lane == 0) {
        out[PRED_OFF + n * 2]     = p0 + b6v[0];
        out[PRED_OFF + n * 2 + 1] = p1 + b6v[1];
    }
}

// ---------------------------------------------------------------------------
extern "C" void kernel_launch(void* const* d_in, const int* in_sizes, int n_in,
                              void* d_out, int out_size)
{
    const float* li  = (const float*)d_in[0];
    const float* gi  = (const float*)d_in[1];
    const float* Wup = (const float*)d_in[2];
    const float* bup = (const float*)d_in[3];
    const float* W1  = (const float*)d_in[4];
    const float* b1  = (const float*)d_in[5];
    const float* W2  = (const float*)d_in[6];
    const float* b2  = (const float*)d_in[7];
    const float* W3  = (const float*)d_in[8];
    const float* b3  = (const float*)d_in[9];
    const float* W4  = (const float*)d_in[10];
    const float* b4  = (const float*)d_in[11];
    const float* W5  = (const float*)d_in[12];
    const float* b5  = (const float*)d_in[13];
    const float* W6  = (const float*)d_in[14];
    const float* b6  = (const float*)d_in[15];
    float* out = (float*)d_out;

    dim3 g1(32, 64);
    k_buildA<<<g1, 256>>>(gi, Wup, bup);
    k_prep<<<80, 256>>>(W1, W2, W3, W4, W5);
    k_warp<<<NSAMP / 4, 128>>>(li, b1, b2, b3, b4, b5, W6, b6, out);
}

// round 6
// speedup vs baseline: 2.8050x; 1.2298x over previous
#include <cuda_runtime.h>
#include <math.h>

// Problem constants
#define NSAMP 4096
#define GD    2016
#define LDF   65

// Output layout: recons [4096,64], pred [4096,2], latent [4096,64]
#define REC_OFF  0
#define PRED_OFF (NSAMP * 64)
#define LAT_OFF  (NSAMP * 64 + NSAMP * 2)

// Packed per-sample vec = gi @ W_up^T + b_up  (coalesced layout, no scatter)
__device__ float g_vec[(size_t)NSAMP * GD];
// Transposed MLP weights: W1,W2,W3,W4,W5 (each 64x64, stored [j][i])
__device__ float g_Wt[5 * 4096];

#define FULLM 0xffffffffu

// ---------------------------------------------------------------------------
// Kernel 1: GEMM [4096,64] x [64,2016]^T -> packed g_vec (fully coalesced out)
// ---------------------------------------------------------------------------
__global__ __launch_bounds__(256) void k_buildA(
    const float* __restrict__ gi,
    const float* __restrict__ Wup,
    const float* __restrict__ bup)
{
    __shared__ float sG[64 * LDF];
    __shared__ float sW[64 * LDF];

    const int tid  = threadIdx.x;
    const int pIdx = blockIdx.x * 64;
    const int sIdx = blockIdx.y * 64;

    for (int lin = tid; lin < 4096; lin += 256) {
        int row = lin >> 6, k = lin & 63;
        sG[row * LDF + k] = gi[(sIdx + row) * 64 + k];
        int p = pIdx + row;
        sW[row * LDF + k] = (p < GD) ? Wup[p * 64 + k] : 0.0f;
    }
    __syncthreads();

    const int cg = tid & 15;
    const int rg = tid >> 4;

    float acc[4][4];
#pragma unroll
    for (int a = 0; a < 4; ++a)
#pragma unroll
        for (int b = 0; b < 4; ++b) acc[a][b] = 0.0f;

#pragma unroll 8
    for (int k = 0; k < 64; ++k) {
        float Ar[4], Br[4];
#pragma unroll
        for (int a = 0; a < 4; ++a) Ar[a] = sG[(rg + 16 * a) * LDF + k];
#pragma unroll
        for (int b = 0; b < 4; ++b) Br[b] = sW[(cg + 16 * b) * LDF + k];
#pragma unroll
        for (int a = 0; a < 4; ++a)
#pragma unroll
            for (int b = 0; b < 4; ++b)
                acc[a][b] = fmaf(Ar[a], Br[b], acc[a][b]);
    }

    // Packed coalesced epilogue: g_vec[s*2016 + p] = acc + bias
#pragma unroll
    for (int b = 0; b < 4; ++b) {
        int p = pIdx + cg + 16 * b;
        if (p >= GD) continue;
        float bb = bup[p];
#pragma unroll
        for (int a = 0; a < 4; ++a) {
            int s = sIdx + rg + 16 * a;
            g_vec[(size_t)s * GD + p] = acc[a][b] + bb;
        }
    }
}

// ---------------------------------------------------------------------------
// Prep: transpose the 5 small MLP weight matrices into g_Wt [j][i]
// ---------------------------------------------------------------------------
__global__ __launch_bounds__(256) void k_prep(
    const float* __restrict__ W1, const float* __restrict__ W2,
    const float* __restrict__ W3, const float* __restrict__ W4,
    const float* __restrict__ W5)
{
    int idx = blockIdx.x * 256 + threadIdx.x;
    if (idx >= 5 * 4096) return;
    int m = idx >> 12;
    int r = idx & 4095;
    int i = r >> 6, j = r & 63;
    const float* W = (m == 0) ? W1 : (m == 1) ? W2 : (m == 2) ? W3 : (m == 3) ? W4 : W5;
    g_Wt[m * 4096 + j * 64 + i] = W[i * 64 + j];
}

// ---------------------------------------------------------------------------
// Warp primitives. Lane owns rows (lane) -> r0[], (lane+32) -> r1[].
// ---------------------------------------------------------------------------
__device__ __forceinline__ void lu64(float (&r0)[64], float (&r1)[64],
                                     float& dinv0, float& dinv1, int lane)
{
#pragma unroll
    for (int k = 0; k < 63; ++k) {
        if (k < 32) {
            float piv  = __shfl_sync(FULLM, r0[k], k);
            float pinv = 1.0f / piv;
            dinv0 = (lane == k) ? pinv : dinv0;
            float l0 = (lane > k) ? r0[k] * pinv : 0.0f;
            r0[k] = (lane > k) ? l0 : r0[k];
            float l1 = r1[k] * pinv;
            r1[k] = l1;
#pragma unroll
            for (int j = k + 1; j < 64; ++j) {
                float bj = __shfl_sync(FULLM, r0[j], k);
                r0[j] = fmaf(-l0, bj, r0[j]);
                r1[j] = fmaf(-l1, bj, r1[j]);
            }
        } else {
            float piv  = __shfl_sync(FULLM, r1[k], k - 32);
            float pinv = 1.0f / piv;
            dinv1 = (lane == k - 32) ? pinv : dinv1;
            float l1 = (lane > k - 32) ? r1[k] * pinv : 0.0f;
            r1[k] = (lane > k - 32) ? l1 : r1[k];
#pragma unroll
            for (int j = k + 1; j < 64; ++j) {
                float bj = __shfl_sync(FULLM, r1[j], k - 32);
                r1[j] = fmaf(-l1, bj, r1[j]);
            }
        }
    }
    {
        float piv  = __shfl_sync(FULLM, r1[63], 31);
        float pinv = 1.0f / piv;
        dinv1 = (lane == 31) ? pinv : dinv1;
    }
}

// Solve (LU) x = b with row-distributed factors (Q-solve).
__device__ __forceinline__ void solve64(const float (&r0)[64], const float (&r1)[64],
                                        float dinv0, float dinv1, int lane,
                                        float b0, float b1, float& x0, float& x1)
{
    float a0 = b0, a1 = b1;
#pragma unroll
    for (int k = 0; k < 64; ++k) {
        if (k < 32) {
            float zk = __shfl_sync(FULLM, a0, k);
            a0 = (lane > k) ? fmaf(-r0[k], zk, a0) : a0;
            a1 = fmaf(-r1[k], zk, a1);
        } else {
            float zk = __shfl_sync(FULLM, a1, k - 32);
            a1 = (lane > k - 32) ? fmaf(-r1[k], zk, a1) : a1;
        }
    }
#pragma unroll
    for (int k = 63; k >= 0; --k) {
        if (k >= 32) {
            float xk = __shfl_sync(FULLM, a1 * dinv1, k - 32);
            x1 = (lane == k - 32) ? xk : x1;
            a1 = (lane < k - 32) ? fmaf(-r1[k], xk, a1) : a1;
            a0 = fmaf(-r0[k], xk, a0);
        } else {
            float xk = __shfl_sync(FULLM, a0 * dinv0, k);
            x0 = (lane == k) ? xk : x0;
            a0 = (lane < k) ? fmaf(-r0[k], xk, a0) : a0;
        }
    }
}

// In-place 32x32 register-block transpose (butterfly block swap).
template<int BASE>
__device__ __forceinline__ void tr32(float (&v)[64], int lane)
{
#pragma unroll
    for (int m = 16; m >= 1; m >>= 1) {
#pragma unroll
        for (int j = 0; j < 32; ++j) {
            if ((j & m) == 0) {
                const int jm = j + m;
                bool up = (lane & m) != 0;
                float send = up ? v[BASE + j] : v[BASE + jm];
                float recv = __shfl_xor_sync(FULLM, send, m);
                if (up) v[BASE + j] = recv; else v[BASE + jm] = recv;
            }
        }
    }
}

// Solve Q^T x = f using the TRANSPOSED (column-distributed) factor copy:
// after in-place tr32 on all 4 blocks:
//   ct0[j] = (j<32 ? r0[j] : r1[j-32])   -- column `lane`   of combined LU
//   ct1[j] = (j<32 ? r0[j+32] : r1[j])   -- column `lane+32` of combined LU
// Q^T = U^T L^T:  forward U^T z = f, backward L^T x = z.
__device__ __forceinline__ void solveT64(const float (&r0)[64], const float (&r1)[64],
                                         float dinv0, float dinv1, int lane,
                                         float f0, float f1, float& x0, float& x1)
{
    float a0 = f0, a1 = f1;
    // forward: U^T (lower tri, diag U(k,k)); U^T(t,k)=U(k,t)=ct_t[k]
#pragma unroll
    for (int k = 0; k < 64; ++k) {
        if (k < 32) {
            float zk = __shfl_sync(FULLM, a0 * dinv0, k);
            a0 = (lane > k) ? fmaf(-r0[k], zk, a0) : a0;        // ct0[k]=r0[k]
            a1 = fmaf(-r0[k + 32], zk, a1);                     // ct1[k]=r0[k+32]
        } else {
            float zk = __shfl_sync(FULLM, a1 * dinv1, k - 32);
            a1 = (lane > k - 32) ? fmaf(-r1[k], zk, a1) : a1;   // ct1[k]=r1[k]
        }
    }
    float z0 = a0 * dinv0;
    float z1 = a1 * dinv1;
    // backward: L^T (unit upper); L^T(t,j)=L(j,t)=ct_t[j], j>t
    a0 = z0; a1 = z1;
#pragma unroll
    for (int j = 63; j >= 0; --j) {
        if (j >= 32) {
            float xj = __shfl_sync(FULLM, a1, j - 32);
            x1 = (lane == j - 32) ? xj : x1;
            a1 = (lane < j - 32) ? fmaf(-r1[j], xj, a1) : a1;   // ct1[j]=r1[j]
            a0 = fmaf(-r1[j - 32], xj, a0);                     // ct0[j]=r1[j-32]
        } else {
            float xj = __shfl_sync(FULLM, a0, j);
            x0 = (lane == j) ? xj : x0;
            a0 = (lane < j) ? fmaf(-r0[j], xj, a0) : a0;        // ct0[j]=r0[j]
        }
    }
}

// y = W x with Wt pre-transposed: y_i = sum_j Wt[j*64+i] * x_j
__device__ __forceinline__ void matvec64(const float* __restrict__ Wt, int lane,
                                         float x0, float x1, float& y0, float& y1)
{
    float a0 = 0.0f, a1 = 0.0f;
#pragma unroll
    for (int j = 0; j < 64; ++j) {
        float xj = (j < 32) ? __shfl_sync(FULLM, x0, j)
                            : __shfl_sync(FULLM, x1, j - 32);
        a0 = fmaf(Wt[j * 64 + lane],      xj, a0);
        a1 = fmaf(Wt[j * 64 + lane + 32], xj, a1);
    }
    y0 = a0; y1 = a1;
}

// ---------------------------------------------------------------------------
// Kernel 2: warp-per-sample. Expand packed vec -> smem A (warp-private),
// ONE register LU of Q = I + A, then:
//   mis    = 2 Q^{-1} li  - li        (row-copy solve)
//   latent = 2 Q^{-T} fc2 - fc2       (transposed-copy solve; B = I-A = Q^T)
// ---------------------------------------------------------------------------
__global__ __launch_bounds__(64) void k_warp(
    const float* __restrict__ li,
    const float* __restrict__ b1v, const float* __restrict__ b2v,
    const float* __restrict__ b3v, const float* __restrict__ b4v,
    const float* __restrict__ b5v,
    const float* __restrict__ W6,  const float* __restrict__ b6v,
    float* __restrict__ out)
{
    __shared__ float sAall[2 * 64 * LDF];   // 2 warps/block, 16.6KB each

    const int lane = threadIdx.x & 31;
    const int wid  = threadIdx.x >> 5;
    const int n    = blockIdx.x * 2 + wid;
    float* sA = sAall + wid * 64 * LDF;

    // ---- Expand packed vec into full skew matrix A in warp-private smem
    const float* __restrict__ vec = g_vec + (size_t)n * GD;
    for (int p = lane; p < GD; p += 32) {
        float v = vec[p];
        float t = sqrtf(8.0f * (float)p + 1.0f);
        int r = (int)((1.0f + t) * 0.5f);
        while (r * (r - 1) / 2 > p) --r;
        while ((r + 1) * r / 2 <= p) ++r;
        int c = p - r * (r - 1) / 2;
        sA[r * LDF + c] = -v;     // A[r][c] = -vec (r>c)
        sA[c * LDF + r] =  v;     // A[c][r] = +vec
    }
    __syncwarp();

    // ---- Build Q = I + A rows (conflict-free LDS: (lane*65+j)%32 distinct)
    float r0[64], r1[64];
    float dinv0 = 1.0f, dinv1 = 1.0f;
#pragma unroll
    for (int j = 0; j < 64; ++j) {
        r0[j] = (j == lane)      ? 1.0f : sA[lane * LDF + j];
        r1[j] = (j == lane + 32) ? 1.0f : sA[(lane + 32) * LDF + j];
    }

    lu64(r0, r1, dinv0, dinv1, lane);

    // ---- mis = 2 Q^{-1} li - li
    float li0 = li[n * 64 + lane];
    float li1 = li[n * 64 + lane + 32];
    float u0 = 0.0f, u1 = 0.0f;
    solve64(r0, r1, dinv0, dinv1, lane, li0, li1, u0, u1);
    float m0 = 2.0f * u0 - li0;
    float m1 = 2.0f * u1 - li1;

    // ---- MLP core
    float h0, h1;
    matvec64(g_Wt + 0 * 4096, lane, m0, m1, h0, h1);
    h0 = fmaxf(h0 + b1v[lane], 0.0f);
    h1 = fmaxf(h1 + b1v[lane + 32], 0.0f);
    float f0, f1;
    matvec64(g_Wt + 1 * 4096, lane, h0, h1, f0, f1);
    f0 += b2v[lane];
    f1 += b2v[lane + 32];

    // ---- In-place transpose of combined LU factors (4 x 32x32 blocks)
    tr32<0 >(r0, lane);
    tr32<32>(r0, lane);
    tr32<0 >(r1, lane);
    tr32<32>(r1, lane);

    // ---- latent = 2 Q^{-T} fc2 - fc2   (B = Q^T)
    float v0 = 0.0f, v1 = 0.0f;
    solveT64(r0, r1, dinv0, dinv1, lane, f0, f1, v0, v1);
    float L0 = 2.0f * v0 - f0;
    float L1 = 2.0f * v1 - f1;
    out[LAT_OFF + n * 64 + lane]      = L0;
    out[LAT_OFF + n * 64 + lane + 32] = L1;

    // ---- recons = W4 relu(W3 latent + b3) + b4
    float t30, t31;
    matvec64(g_Wt + 2 * 4096, lane, L0, L1, t30, t31);
    t30 = fmaxf(t30 + b3v[lane], 0.0f);
    t31 = fmaxf(t31 + b3v[lane + 32], 0.0f);
    float rc0, rc1;
    matvec64(g_Wt + 3 * 4096, lane, t30, t31, rc0, rc1);
    out[REC_OFF + n * 64 + lane]      = rc0 + b4v[lane];
    out[REC_OFF + n * 64 + lane + 32] = rc1 + b4v[lane + 32];

    // ---- pred = W6 relu(W5 latent + b5) + b6
    float t50, t51;
    matvec64(g_Wt + 4 * 4096, lane, L0, L1, t50, t51);
    t50 = fmaxf(t50 + b5v[lane], 0.0f);
    t51 = fmaxf(t51 + b5v[lane + 32], 0.0f);
    float p0 = W6[lane] * t50      + W6[32 + lane] * t51;
    float p1 = W6[64 + lane] * t50 + W6[96 + lane] * t51;
#pragma unroll
    for (int off = 16; off; off >>= 1) {
        p0 += __shfl_xor_sync(FULLM, p0, off);
        p1 += __shfl_xor_sync(FULLM, p1, off);
    }
    if (lane == 0) {
        out[PRED_OFF + n * 2]     = p0 + b6v[0];
        out[PRED_OFF + n * 2 + 1] = p1 + b6v[1];
    }
}

// ---------------------------------------------------------------------------
extern "C" void kernel_launch(void* const* d_in, const int* in_sizes, int n_in,
                              void* d_out, int out_size)
{
    const float* li  = (const float*)d_in[0];
    const float* gi  = (const float*)d_in[1];
    const float* Wup = (const float*)d_in[2];
    const float* bup = (const float*)d_in[3];
    const float* W1  = (const float*)d_in[4];
    const float* b1  = (const float*)d_in[5];
    const float* W2  = (const float*)d_in[6];
    const float* b2  = (const float*)d_in[7];
    const float* W3  = (const float*)d_in[8];
    const float* b3  = (const float*)d_in[9];
    const float* W4  = (const float*)d_in[10];
    const float* b4  = (const float*)d_in[11];
    const float* W5  = (const float*)d_in[12];
    const float* b5  = (const float*)d_in[13];
    const float* W6  = (const float*)d_in[14];
    const float* b6  = (const float*)d_in[15];
    float* out = (float*)d_out;

    dim3 g1(32, 64);
    k_buildA<<<g1, 256>>>(gi, Wup, bup);
    k_prep<<<80, 256>>>(W1, W2, W3, W4, W5);
    k_warp<<<NSAMP / 2, 64>>>(li, b1, b2, b3, b4, b5, W6, b6, out);
}